// round 2
// baseline (speedup 1.0000x reference)
#include <cuda_runtime.h>
#include <cstdint>

#define U64 unsigned long long

// ---------------- scratch (static device memory; no allocation) ----------------
// Wt[x][j][i*32+c] = W[x,i,c,j] (complex interleaved)       33.5 MB
__device__ float2 g_Wt[128u*32u*1024u];
// Hf[x][b*32+i][t] = fftshift(fft_x(Hu))[b,i,x,t]           67 MB
__device__ float2 g_Hf[128u*256u*256u];
// Z0f[x][b*32+i]   = fftshift(fft_x(z0))[b,i,x]             256 KB
__device__ float2 g_Z0f[128u*256u];
// Zs[b*32+i][t][x] = z_t[b,x,i] (shifted freq domain)        67 MB
__device__ float2 g_Zs[256u*256u*128u];
__device__ float  g_Fz[256u*128u];       // (A z0)[b,i,x]
__device__ float  g_Gz[256u*8u*128u];    // (Gw z0)[b,i,f,x]

// ---------------- helpers ----------------
__device__ __forceinline__ U64 pk2(float lo, float hi){
    U64 r; asm("mov.b64 %0, {%1, %2};" : "=l"(r) : "f"(lo), "f"(hi)); return r;
}
__device__ __forceinline__ float2 upk2(U64 v){
    float lo, hi; asm("mov.b64 {%0, %1}, %2;" : "=f"(lo), "=f"(hi) : "l"(v));
    return make_float2(lo, hi);
}
// packed dual-fp32 FMA: acc += a*b elementwise on 2 lanes
#define FMA2(acc, a, b) asm("fma.rn.f32x2 %0, %1, %2, %0;" : "+l"(acc) : "l"(a), "l"(b))

__device__ __forceinline__ int rev7(int v){ return (int)(__brev((unsigned)v) >> 25); }

__device__ __forceinline__ void build_tw(float2* tw, int tid, float sign){
    if (tid < 64){
        float ang = sign * 6.28318530717958647692f * (float)tid * (1.0f/128.0f);
        float s, c; __sincosf(ang, &s, &c);
        tw[tid] = make_float2(c, s);
    }
}

// in-place radix-2 DIT FFT on nt rows of 128 (input bit-reversed, output natural)
__device__ __forceinline__ void fft_inplace(float2* buf, int nt, const float2* tw,
                                            int tid, int nth){
    #pragma unroll
    for (int s = 0; s < 7; s++){
        int half = 1 << s;
        int nbf = nt << 6;
        for (int idx = tid; idx < nbf; idx += nth){
            int q   = idx & 63;
            int row = idx >> 6;
            int p   = q & (half - 1);
            int g   = q >> s;
            int i0  = row * 128 + g * (half << 1) + p;
            float2 a = buf[i0], b = buf[i0 + half];
            float2 w = tw[p << (6 - s)];
            float2 t = make_float2(w.x*b.x - w.y*b.y, w.x*b.y + w.y*b.x);
            buf[i0]        = make_float2(a.x + t.x, a.y + t.y);
            buf[i0 + half] = make_float2(a.x - t.x, a.y - t.y);
        }
        __syncthreads();
    }
}

// ---------------- K0: transpose W into scan-coalesced layout ----------------
// grid (128, 32) = (x, i), 1024 threads
__global__ void k0_wt(const float* __restrict__ Wr, const float* __restrict__ Wi){
    __shared__ float2 s[32][33];
    int x = blockIdx.x, i = blockIdx.y;
    int tid = threadIdx.x;
    int c = tid >> 5, j = tid & 31;
    size_t base = (((size_t)(x*32 + i))*32 + c)*32 + j;
    s[c][j] = make_float2(Wr[base], Wi[base]);
    __syncthreads();
    int j2 = tid >> 5, c2 = tid & 31;
    g_Wt[(size_t)x*32768 + (size_t)j2*1024 + i*32 + c2] = s[c2][j2];
}

// ---------------- K1: Fz0 = A z0, Gz0 = Gw z0 ----------------
// grid 256 (b*32+i), 128 threads (x)
__global__ void k1_proj(const float* __restrict__ z0, const float* __restrict__ A,
                        const float* __restrict__ Gw){
    int bi = blockIdx.x; int b = bi >> 5, i = bi & 31;
    int x = threadIdx.x;
    float zv[32];
    #pragma unroll
    for (int h = 0; h < 32; h++) zv[h] = z0[((size_t)(b*32 + h))*128 + x];
    float f = 0.f;
    #pragma unroll
    for (int h = 0; h < 32; h++) f += A[i*32 + h] * zv[h];
    g_Fz[bi*128 + x] = f;
    for (int fi = 0; fi < 8; fi++){
        float g = 0.f;
        #pragma unroll
        for (int h = 0; h < 32; h++) g += Gw[(i*8 + fi)*32 + h] * zv[h];
        g_Gz[(bi*8 + fi)*128 + x] = g;
    }
}

// ---------------- K2b: fftshift(fft_x(z0)) ----------------
// grid 256 (bi), 128 threads
__global__ void k2b_z0fft(const float* __restrict__ z0){
    __shared__ float2 buf[128];
    __shared__ float2 tw[64];
    int bi = blockIdx.x;
    int tid = threadIdx.x;
    build_tw(tw, tid, -1.f);
    buf[rev7(tid)] = make_float2(z0[(size_t)bi*128 + tid], 0.f);
    __syncthreads();
    fft_inplace(buf, 1, tw, tid, 128);
    int xs = (tid + 64) & 127;
    g_Z0f[xs*256 + bi] = buf[tid];
}

// ---------------- K2: Hu + FFT_x + shift -> g_Hf ----------------
// grid (256, 16) = (bi, t-tile of 16), 256 threads
__global__ void k2_hufft(const float* __restrict__ xi){
    __shared__ float2 buf[16*128];
    __shared__ float  Gl[8*128];
    __shared__ float  Fl[128];
    __shared__ float2 tw[64];
    int bi = blockIdx.x; int b = bi >> 5;
    int t0 = blockIdx.y * 16;
    int tid = threadIdx.x;
    build_tw(tw, tid, -1.f);
    if (tid < 128) Fl[tid] = g_Fz[bi*128 + tid];
    for (int idx = tid; idx < 1024; idx += 256) Gl[idx] = g_Gz[(size_t)bi*1024 + idx];
    __syncthreads();
    #pragma unroll
    for (int k = 0; k < 8; k++){
        int idx = tid + k*256;
        int tt = idx & 15, x = idx >> 4;
        float hu = Fl[x];
        #pragma unroll
        for (int f = 0; f < 8; f++)
            hu += Gl[f*128 + x] * xi[((size_t)(b*8 + f)*128 + x)*256 + t0 + tt];
        buf[tt*128 + rev7(x)] = make_float2(hu, 0.f);
    }
    __syncthreads();
    fft_inplace(buf, 16, tw, tid, 256);
    #pragma unroll
    for (int k = 0; k < 8; k++){
        int idx = tid + k*256;
        int tt = idx & 15, xk = idx >> 4;
        int xs = (xk + 64) & 127;
        g_Hf[(size_t)xs*65536 + (size_t)bi*256 + t0 + tt] = buf[tt*128 + xk];
    }
}

// ---------------- K3: sequential CDE scan (dominant kernel) ----------------
// grid 128 (x), 1024 threads; thread = (i = warp, c = lane); batches b packed in pairs
__global__ __launch_bounds__(1024, 1) void k3_scan(){
    __shared__ float2 s_zc[256];       // z[b*32+j]
    __shared__ U64    s_zrp[128];      // (z[2bp][j].re, z[2bp+1][j].re) at [bp*32+j]
    __shared__ U64    s_zip[128];      // imag counterpart
    __shared__ float2 s_dx[256];       // dx[b*32+c]
    int x    = blockIdx.x;
    int tid  = threadIdx.x;
    int lane = tid & 31;   // c
    int wi   = tid >> 5;   // i
    const float2* WtX = g_Wt + (size_t)x*32768 + tid;
    float2 hcur = make_float2(0.f, 0.f);
    if (tid < 256){
        s_zc[tid] = g_Z0f[x*256 + tid];
        hcur = g_Hf[(size_t)x*65536 + (size_t)tid*256];
    }
    __syncthreads();
    if (tid < 128){
        int bp = tid >> 5, j = tid & 31;
        float2 ze = s_zc[(2*bp)*32 + j];
        float2 zo = s_zc[(2*bp + 1)*32 + j];
        s_zrp[tid] = pk2(ze.x, zo.x);
        s_zip[tid] = pk2(ze.y, zo.y);
    }
    __syncthreads();

    for (int t = 0; t < 255; t++){
        if (tid < 256){
            g_Zs[(size_t)tid*32768 + (size_t)t*128 + x] = s_zc[tid];
            float2 hn = g_Hf[(size_t)x*65536 + (size_t)tid*256 + (t + 1)];
            s_dx[tid] = make_float2(hn.x - hcur.x, hn.y - hcur.y);
            hcur = hn;
        }
        __syncthreads();

        // fz[b, i=wi, c=lane] = sum_j W[x,i,c,j] * z[b,j]   (b-pairs packed f32x2)
        U64 aRa[4] = {0,0,0,0}, aRb[4] = {0,0,0,0};
        U64 aIa[4] = {0,0,0,0}, aIb[4] = {0,0,0,0};
        #pragma unroll 8
        for (int j = 0; j < 32; j++){
            float2 w = WtX[(size_t)j*1024];
            U64 wrr = pk2(w.x, w.x);
            U64 wii = pk2(w.y, w.y);
            #pragma unroll
            for (int bp = 0; bp < 4; bp++){
                U64 zr = s_zrp[bp*32 + j];
                U64 zi = s_zip[bp*32 + j];
                FMA2(aRa[bp], wrr, zr);
                FMA2(aRb[bp], wii, zi);
                FMA2(aIa[bp], wrr, zi);
                FMA2(aIb[bp], wii, zr);
            }
        }
        // contrib[b] = fz[b] * dx[b, c]
        float cR[8], cI[8];
        #pragma unroll
        for (int bp = 0; bp < 4; bp++){
            float2 ra = upk2(aRa[bp]), rb = upk2(aRb[bp]);
            float2 ia = upk2(aIa[bp]), ib = upk2(aIb[bp]);
            float fr0 = ra.x - rb.x, fi0 = ia.x + ib.x;
            float fr1 = ra.y - rb.y, fi1 = ia.y + ib.y;
            float2 d0 = s_dx[(2*bp)*32 + lane];
            float2 d1 = s_dx[(2*bp + 1)*32 + lane];
            cR[2*bp]     = fr0*d0.x - fi0*d0.y;
            cI[2*bp]     = fr0*d0.y + fi0*d0.x;
            cR[2*bp + 1] = fr1*d1.x - fi1*d1.y;
            cI[2*bp + 1] = fr1*d1.y + fi1*d1.x;
        }
        // reduce over c (lanes)
        #pragma unroll
        for (int off = 16; off >= 1; off >>= 1){
            #pragma unroll
            for (int b = 0; b < 8; b++){
                cR[b] += __shfl_xor_sync(0xffffffffu, cR[b], off);
                cI[b] += __shfl_xor_sync(0xffffffffu, cI[b], off);
            }
        }
        __syncthreads();   // all reads of z arrays done before update
        if (lane < 8){
            float sr = cR[0], si = cI[0];
            #pragma unroll
            for (int b = 1; b < 8; b++){ if (lane == b){ sr = cR[b]; si = cI[b]; } }
            int idxz = lane*32 + wi;
            float2 zo = s_zc[idxz];
            float2 zn = make_float2(zo.x + sr, zo.y + si);
            s_zc[idxz] = zn;
            int pp = ((lane >> 1)*32 + wi)*2 + (lane & 1);
            ((float*)s_zrp)[pp] = zn.x;
            ((float*)s_zip)[pp] = zn.y;
        }
        __syncthreads();
    }
    if (tid < 256){
        g_Zs[(size_t)tid*32768 + (size_t)255*128 + x] = s_zc[tid];
    }
}

// ---------------- K4: ifftshift + IFFT_x + real part -> out ----------------
// grid (256, 16) = (bi, t-tile), 256 threads
__global__ void k4_ifft(float* __restrict__ out){
    __shared__ float2 buf[16*128];
    __shared__ float2 tw[64];
    int bi = blockIdx.x;
    int t0 = blockIdx.y * 16;
    int tid = threadIdx.x;
    build_tw(tw, tid, +1.f);
    #pragma unroll
    for (int k = 0; k < 8; k++){
        int idx = tid + k*256;
        int m = idx & 127, tt = idx >> 7;
        float2 v = g_Zs[(size_t)bi*32768 + (size_t)(t0 + tt)*128 + ((m + 64) & 127)];
        buf[tt*128 + rev7(m)] = v;
    }
    __syncthreads();
    fft_inplace(buf, 16, tw, tid, 256);
    #pragma unroll
    for (int k = 0; k < 8; k++){
        int idx = tid + k*256;
        int tt = idx & 15, n = idx >> 4;
        out[((size_t)bi*128 + n)*256 + t0 + tt] = buf[tt*128 + n].x * (1.0f/128.0f);
    }
}

// ---------------- launch ----------------
extern "C" void kernel_launch(void* const* d_in, const int* in_sizes, int n_in,
                              void* d_out, int out_size){
    const float* z0 = (const float*)d_in[0];
    const float* xi = (const float*)d_in[1];
    const float* A  = (const float*)d_in[2];
    const float* Gw = (const float*)d_in[3];
    const float* Wr = (const float*)d_in[4];
    const float* Wi = (const float*)d_in[5];
    float* out = (float*)d_out;

    k0_wt<<<dim3(128, 32), 1024>>>(Wr, Wi);
    k1_proj<<<256, 128>>>(z0, A, Gw);
    k2b_z0fft<<<256, 128>>>(z0);
    k2_hufft<<<dim3(256, 16), 256>>>(xi);
    k3_scan<<<128, 1024>>>();
    k4_ifft<<<dim3(256, 16), 256>>>(out);
    (void)in_sizes; (void)n_in; (void)out_size;
}

// round 3
// speedup vs baseline: 1.0550x; 1.0550x over previous
#include <cuda_runtime.h>
#include <cstdint>

#define U64 unsigned long long

// ---------------- scratch (static device memory; no allocation) ----------------
__device__ float2 g_Wt[128u*32u*1024u];   // Wt[x][j][i*32+c] = W[x,i,c,j]
__device__ float2 g_Hf[128u*256u*256u];   // Hf[x][b*32+i][t]
__device__ float2 g_Z0f[128u*256u];       // Z0f[x][b*32+i]
__device__ float2 g_Zs[256u*256u*128u];   // Zs[b*32+i][t][x]
__device__ float  g_Fz[256u*128u];
__device__ float  g_Gz[256u*8u*128u];

// ---------------- helpers ----------------
__device__ __forceinline__ U64 pk2(float lo, float hi){
    U64 r; asm("mov.b64 %0, {%1, %2};" : "=l"(r) : "f"(lo), "f"(hi)); return r;
}
__device__ __forceinline__ float2 upk2(U64 v){
    float lo, hi; asm("mov.b64 {%0, %1}, %2;" : "=f"(lo), "=f"(hi) : "l"(v));
    return make_float2(lo, hi);
}
#define FMA2(acc, a, b) asm("fma.rn.f32x2 %0, %1, %2, %0;" : "+l"(acc) : "l"(a), "l"(b))

__device__ __forceinline__ int rev7(int v){ return (int)(__brev((unsigned)v) >> 25); }

__device__ __forceinline__ void build_tw(float2* tw, int tid, float sign){
    if (tid < 64){
        float ang = sign * 6.28318530717958647692f * (float)tid * (1.0f/128.0f);
        float s, c; __sincosf(ang, &s, &c);
        tw[tid] = make_float2(c, s);
    }
}

__device__ __forceinline__ void fft_inplace(float2* buf, int nt, const float2* tw,
                                            int tid, int nth){
    #pragma unroll
    for (int s = 0; s < 7; s++){
        int half = 1 << s;
        int nbf = nt << 6;
        for (int idx = tid; idx < nbf; idx += nth){
            int q   = idx & 63;
            int row = idx >> 6;
            int p   = q & (half - 1);
            int g   = q >> s;
            int i0  = row * 128 + g * (half << 1) + p;
            float2 a = buf[i0], b = buf[i0 + half];
            float2 w = tw[p << (6 - s)];
            float2 t = make_float2(w.x*b.x - w.y*b.y, w.x*b.y + w.y*b.x);
            buf[i0]        = make_float2(a.x + t.x, a.y + t.y);
            buf[i0 + half] = make_float2(a.x - t.x, a.y - t.y);
        }
        __syncthreads();
    }
}

// ---------------- K0: transpose W ----------------
__global__ void k0_wt(const float* __restrict__ Wr, const float* __restrict__ Wi){
    __shared__ float2 s[32][33];
    int x = blockIdx.x, i = blockIdx.y;
    int tid = threadIdx.x;
    int c = tid >> 5, j = tid & 31;
    size_t base = (((size_t)(x*32 + i))*32 + c)*32 + j;
    s[c][j] = make_float2(Wr[base], Wi[base]);
    __syncthreads();
    int j2 = tid >> 5, c2 = tid & 31;
    g_Wt[(size_t)x*32768 + (size_t)j2*1024 + i*32 + c2] = s[c2][j2];
}

// ---------------- K1 ----------------
__global__ void k1_proj(const float* __restrict__ z0, const float* __restrict__ A,
                        const float* __restrict__ Gw){
    int bi = blockIdx.x; int b = bi >> 5, i = bi & 31;
    int x = threadIdx.x;
    float zv[32];
    #pragma unroll
    for (int h = 0; h < 32; h++) zv[h] = z0[((size_t)(b*32 + h))*128 + x];
    float f = 0.f;
    #pragma unroll
    for (int h = 0; h < 32; h++) f += A[i*32 + h] * zv[h];
    g_Fz[bi*128 + x] = f;
    for (int fi = 0; fi < 8; fi++){
        float g = 0.f;
        #pragma unroll
        for (int h = 0; h < 32; h++) g += Gw[(i*8 + fi)*32 + h] * zv[h];
        g_Gz[(bi*8 + fi)*128 + x] = g;
    }
}

// ---------------- K2b ----------------
__global__ void k2b_z0fft(const float* __restrict__ z0){
    __shared__ float2 buf[128];
    __shared__ float2 tw[64];
    int bi = blockIdx.x;
    int tid = threadIdx.x;
    build_tw(tw, tid, -1.f);
    buf[rev7(tid)] = make_float2(z0[(size_t)bi*128 + tid], 0.f);
    __syncthreads();
    fft_inplace(buf, 1, tw, tid, 128);
    int xs = (tid + 64) & 127;
    g_Z0f[xs*256 + bi] = buf[tid];
}

// ---------------- K2 ----------------
__global__ void k2_hufft(const float* __restrict__ xi){
    __shared__ float2 buf[16*128];
    __shared__ float  Gl[8*128];
    __shared__ float  Fl[128];
    __shared__ float2 tw[64];
    int bi = blockIdx.x; int b = bi >> 5;
    int t0 = blockIdx.y * 16;
    int tid = threadIdx.x;
    build_tw(tw, tid, -1.f);
    if (tid < 128) Fl[tid] = g_Fz[bi*128 + tid];
    for (int idx = tid; idx < 1024; idx += 256) Gl[idx] = g_Gz[(size_t)bi*1024 + idx];
    __syncthreads();
    #pragma unroll
    for (int k = 0; k < 8; k++){
        int idx = tid + k*256;
        int tt = idx & 15, x = idx >> 4;
        float hu = Fl[x];
        #pragma unroll
        for (int f = 0; f < 8; f++)
            hu += Gl[f*128 + x] * xi[((size_t)(b*8 + f)*128 + x)*256 + t0 + tt];
        buf[tt*128 + rev7(x)] = make_float2(hu, 0.f);
    }
    __syncthreads();
    fft_inplace(buf, 16, tw, tid, 256);
    #pragma unroll
    for (int k = 0; k < 8; k++){
        int idx = tid + k*256;
        int tt = idx & 15, xk = idx >> 4;
        int xs = (xk + 64) & 127;
        g_Hf[(size_t)xs*65536 + (size_t)bi*256 + t0 + tt] = buf[tt*128 + xk];
    }
}

// ---------------- K3: sequential CDE scan ----------------
// grid 128 (x), 1024 threads; thread = (i = warp, c = lane)
// Gauss 3-mult complex MAC, b packed in f32x2 pairs, z in LDS.128 quads
__global__ __launch_bounds__(1024, 1) void k3_scan(){
    __shared__ float2     s_zc[256];      // canonical z[b*32+j]
    __shared__ ulonglong2 s_zq[32][6];    // per j: {r01|r23, r45|r67, i01|i23, i45|i67, s01|s23, s45|s67}
    __shared__ float2     s_dx[256];      // dx[b*32+c]
    int x    = blockIdx.x;
    int tid  = threadIdx.x;
    int lane = tid & 31;   // c
    int wi   = tid >> 5;   // i
    const float2* WtX = g_Wt + (size_t)x*32768 + tid;
    float2 hcur = make_float2(0.f,0.f), hn = make_float2(0.f,0.f);
    if (tid < 256){
        s_zc[tid] = g_Z0f[x*256 + tid];
        hcur = g_Hf[(size_t)x*65536 + (size_t)tid*256 + 0];
        hn   = g_Hf[(size_t)x*65536 + (size_t)tid*256 + 1];
    }
    __syncthreads();
    // build quads: 192 writers, each one ulonglong2
    if (tid < 192){
        int j = tid / 6, q = tid % 6;
        int cls = q >> 1;          // 0=r, 1=i, 2=s
        int bh  = (q & 1) * 4;     // base b
        float f[4];
        #pragma unroll
        for (int w = 0; w < 4; w++){
            float2 z = s_zc[(bh + w)*32 + j];
            f[w] = (cls == 0) ? z.x : (cls == 1) ? z.y : (z.x + z.y);
        }
        ulonglong2 v; v.x = pk2(f[0], f[1]); v.y = pk2(f[2], f[3]);
        s_zq[j][q] = v;
    }
    __syncthreads();

    bool t4 = (lane & 16) != 0, t3 = (lane & 8) != 0;
    bool t2 = (lane & 4)  != 0, t1 = (lane & 2) != 0;

    for (int t = 0; t < 255; t++){
        if (tid < 256){
            g_Zs[(size_t)tid*32768 + (size_t)t*128 + x] = s_zc[tid];
            s_dx[tid] = make_float2(hn.x - hcur.x, hn.y - hcur.y);
            hcur = hn;
        }
        __syncthreads();
        if (tid < 256){
            int tn = (t + 2 < 256) ? t + 2 : 255;
            hn = g_Hf[(size_t)x*65536 + (size_t)tid*256 + tn];
        }

        // P = sum wr*zr ; Q = sum wi*zi ; S = sum (wr+wi)*(zr+zi)   (b-pairs packed)
        U64 P[4] = {0,0,0,0}, Q[4] = {0,0,0,0}, S[4] = {0,0,0,0};
        #pragma unroll 4
        for (int j = 0; j < 32; j++){
            float2 w = WtX[(size_t)j*1024];
            U64 wrr = pk2(w.x, w.x);
            U64 wii = pk2(w.y, w.y);
            float ws = w.x + w.y;
            U64 wss = pk2(ws, ws);
            ulonglong2 zr2a = s_zq[j][0], zr2b = s_zq[j][1];
            ulonglong2 zi2a = s_zq[j][2], zi2b = s_zq[j][3];
            ulonglong2 zs2a = s_zq[j][4], zs2b = s_zq[j][5];
            FMA2(P[0], wrr, zr2a.x); FMA2(P[1], wrr, zr2a.y);
            FMA2(P[2], wrr, zr2b.x); FMA2(P[3], wrr, zr2b.y);
            FMA2(Q[0], wii, zi2a.x); FMA2(Q[1], wii, zi2a.y);
            FMA2(Q[2], wii, zi2b.x); FMA2(Q[3], wii, zi2b.y);
            FMA2(S[0], wss, zs2a.x); FMA2(S[1], wss, zs2a.y);
            FMA2(S[2], wss, zs2b.x); FMA2(S[3], wss, zs2b.y);
        }

        // epilogue: fz = (P-Q) + i(S-P-Q); contrib = fz * dx[b, c]
        float v[16];
        #pragma unroll
        for (int k = 0; k < 4; k++){
            float2 p = upk2(P[k]), q = upk2(Q[k]), s = upk2(S[k]);
            int b0 = 2*k, b1 = 2*k + 1;
            float fr0 = p.x - q.x, fi0 = s.x - p.x - q.x;
            float fr1 = p.y - q.y, fi1 = s.y - p.y - q.y;
            float2 d0 = s_dx[b0*32 + lane];
            float2 d1 = s_dx[b1*32 + lane];
            v[b0*2]     = fr0*d0.x - fi0*d0.y;
            v[b0*2 + 1] = fr0*d0.y + fi0*d0.x;
            v[b1*2]     = fr1*d1.x - fi1*d1.y;
            v[b1*2 + 1] = fr1*d1.y + fi1*d1.x;
        }

        // value-halving butterfly: 16 values summed over 32 lanes (31 shfl)
        #pragma unroll
        for (int m = 0; m < 8; m++){
            float a0 = v[m]     + __shfl_xor_sync(0xffffffffu, v[m],     16);
            float a1 = v[m + 8] + __shfl_xor_sync(0xffffffffu, v[m + 8], 16);
            v[m] = t4 ? a1 : a0;
        }
        #pragma unroll
        for (int m = 0; m < 4; m++){
            float a0 = v[m]     + __shfl_xor_sync(0xffffffffu, v[m],     8);
            float a1 = v[m + 4] + __shfl_xor_sync(0xffffffffu, v[m + 4], 8);
            v[m] = t3 ? a1 : a0;
        }
        #pragma unroll
        for (int m = 0; m < 2; m++){
            float a0 = v[m]     + __shfl_xor_sync(0xffffffffu, v[m],     4);
            float a1 = v[m + 2] + __shfl_xor_sync(0xffffffffu, v[m + 2], 4);
            v[m] = t2 ? a1 : a0;
        }
        {
            float a0 = v[0] + __shfl_xor_sync(0xffffffffu, v[0], 2);
            float a1 = v[1] + __shfl_xor_sync(0xffffffffu, v[1], 2);
            v[0] = t1 ? a1 : a0;
        }
        v[0] += __shfl_xor_sync(0xffffffffu, v[0], 1);
        // lane l now holds total for b = (l>>2)&7, comp = (l>>1)&1 (dup over bit0)

        __syncthreads();   // all reads of z done before update
        if (!(lane & 1)){
            int b    = (lane >> 2) & 7;
            int comp = (lane >> 1) & 1;
            float* zc = (float*)&s_zc[b*32 + wi];
            float nv = zc[comp] + v[0];
            zc[comp] = nv;
            float other = __shfl_xor_sync(0x55555555u, nv, 2);
            float* zqf = (float*)s_zq[wi];   // [0..7]=r, [8..15]=i, [16..23]=s  (index b)
            zqf[comp*8 + b] = nv;
            if (comp == 0) zqf[16 + b] = nv + other;
        }
        __syncthreads();
    }
    if (tid < 256){
        g_Zs[(size_t)tid*32768 + (size_t)255*128 + x] = s_zc[tid];
    }
}

// ---------------- K4 ----------------
__global__ void k4_ifft(float* __restrict__ out){
    __shared__ float2 buf[16*128];
    __shared__ float2 tw[64];
    int bi = blockIdx.x;
    int t0 = blockIdx.y * 16;
    int tid = threadIdx.x;
    build_tw(tw, tid, +1.f);
    #pragma unroll
    for (int k = 0; k < 8; k++){
        int idx = tid + k*256;
        int m = idx & 127, tt = idx >> 7;
        float2 v = g_Zs[(size_t)bi*32768 + (size_t)(t0 + tt)*128 + ((m + 64) & 127)];
        buf[tt*128 + rev7(m)] = v;
    }
    __syncthreads();
    fft_inplace(buf, 16, tw, tid, 256);
    #pragma unroll
    for (int k = 0; k < 8; k++){
        int idx = tid + k*256;
        int tt = idx & 15, n = idx >> 4;
        out[((size_t)bi*128 + n)*256 + t0 + tt] = buf[tt*128 + n].x * (1.0f/128.0f);
    }
}

// ---------------- launch ----------------
extern "C" void kernel_launch(void* const* d_in, const int* in_sizes, int n_in,
                              void* d_out, int out_size){
    const float* z0 = (const float*)d_in[0];
    const float* xi = (const float*)d_in[1];
    const float* A  = (const float*)d_in[2];
    const float* Gw = (const float*)d_in[3];
    const float* Wr = (const float*)d_in[4];
    const float* Wi = (const float*)d_in[5];
    float* out = (float*)d_out;

    k0_wt<<<dim3(128, 32), 1024>>>(Wr, Wi);
    k1_proj<<<256, 128>>>(z0, A, Gw);
    k2b_z0fft<<<256, 128>>>(z0);
    k2_hufft<<<dim3(256, 16), 256>>>(xi);
    k3_scan<<<128, 1024>>>();
    k4_ifft<<<dim3(256, 16), 256>>>(out);
    (void)in_sizes; (void)n_in; (void)out_size;
}

// round 4
// speedup vs baseline: 1.0742x; 1.0182x over previous
#include <cuda_runtime.h>
#include <cstdint>

#define U64 unsigned long long

// ---------------- scratch (static device memory; no allocation) ----------------
__device__ float2 g_Wt[128u*32u*1024u];   // Wt[x][j][i*32+c] = W[x,i,c,j]
__device__ float2 g_Hf[128u*256u*256u];   // Hf[x][b*32+i][t]
__device__ float2 g_Z0f[128u*256u];       // Z0f[x][b*32+i]
__device__ float2 g_Zs[256u*256u*128u];   // Zs[b*32+i][t][x]
__device__ float  g_Fz[256u*128u];
__device__ float  g_Gz[256u*8u*128u];

// ---------------- helpers ----------------
__device__ __forceinline__ U64 pk2(float lo, float hi){
    U64 r; asm("mov.b64 %0, {%1, %2};" : "=l"(r) : "f"(lo), "f"(hi)); return r;
}
__device__ __forceinline__ float2 upk2(U64 v){
    float lo, hi; asm("mov.b64 {%0, %1}, %2;" : "=f"(lo), "=f"(hi) : "l"(v));
    return make_float2(lo, hi);
}
#define FMA2(acc, a, b) asm("fma.rn.f32x2 %0, %1, %2, %0;" : "+l"(acc) : "l"(a), "l"(b))

__device__ __forceinline__ int rev7(int v){ return (int)(__brev((unsigned)v) >> 25); }

__device__ __forceinline__ void build_tw(float2* tw, int tid, float sign){
    if (tid < 64){
        float ang = sign * 6.28318530717958647692f * (float)tid * (1.0f/128.0f);
        float s, c; __sincosf(ang, &s, &c);
        tw[tid] = make_float2(c, s);
    }
}

__device__ __forceinline__ void fft_inplace(float2* buf, int nt, const float2* tw,
                                            int tid, int nth){
    #pragma unroll
    for (int s = 0; s < 7; s++){
        int half = 1 << s;
        int nbf = nt << 6;
        for (int idx = tid; idx < nbf; idx += nth){
            int q   = idx & 63;
            int row = idx >> 6;
            int p   = q & (half - 1);
            int g   = q >> s;
            int i0  = row * 128 + g * (half << 1) + p;
            float2 a = buf[i0], b = buf[i0 + half];
            float2 w = tw[p << (6 - s)];
            float2 t = make_float2(w.x*b.x - w.y*b.y, w.x*b.y + w.y*b.x);
            buf[i0]        = make_float2(a.x + t.x, a.y + t.y);
            buf[i0 + half] = make_float2(a.x - t.x, a.y - t.y);
        }
        __syncthreads();
    }
}

// ---------------- K0: transpose W ----------------
__global__ void k0_wt(const float* __restrict__ Wr, const float* __restrict__ Wi){
    __shared__ float2 s[32][33];
    int x = blockIdx.x, i = blockIdx.y;
    int tid = threadIdx.x;
    int c = tid >> 5, j = tid & 31;
    size_t base = (((size_t)(x*32 + i))*32 + c)*32 + j;
    s[c][j] = make_float2(Wr[base], Wi[base]);
    __syncthreads();
    int j2 = tid >> 5, c2 = tid & 31;
    g_Wt[(size_t)x*32768 + (size_t)j2*1024 + i*32 + c2] = s[c2][j2];
}

// ---------------- K1 ----------------
__global__ void k1_proj(const float* __restrict__ z0, const float* __restrict__ A,
                        const float* __restrict__ Gw){
    int bi = blockIdx.x; int b = bi >> 5, i = bi & 31;
    int x = threadIdx.x;
    float zv[32];
    #pragma unroll
    for (int h = 0; h < 32; h++) zv[h] = z0[((size_t)(b*32 + h))*128 + x];
    float f = 0.f;
    #pragma unroll
    for (int h = 0; h < 32; h++) f += A[i*32 + h] * zv[h];
    g_Fz[bi*128 + x] = f;
    for (int fi = 0; fi < 8; fi++){
        float g = 0.f;
        #pragma unroll
        for (int h = 0; h < 32; h++) g += Gw[(i*8 + fi)*32 + h] * zv[h];
        g_Gz[(bi*8 + fi)*128 + x] = g;
    }
}

// ---------------- K2b ----------------
__global__ void k2b_z0fft(const float* __restrict__ z0){
    __shared__ float2 buf[128];
    __shared__ float2 tw[64];
    int bi = blockIdx.x;
    int tid = threadIdx.x;
    build_tw(tw, tid, -1.f);
    buf[rev7(tid)] = make_float2(z0[(size_t)bi*128 + tid], 0.f);
    __syncthreads();
    fft_inplace(buf, 1, tw, tid, 128);
    int xs = (tid + 64) & 127;
    g_Z0f[xs*256 + bi] = buf[tid];
}

// ---------------- K2 ----------------
__global__ void k2_hufft(const float* __restrict__ xi){
    __shared__ float2 buf[16*128];
    __shared__ float  Gl[8*128];
    __shared__ float  Fl[128];
    __shared__ float2 tw[64];
    int bi = blockIdx.x; int b = bi >> 5;
    int t0 = blockIdx.y * 16;
    int tid = threadIdx.x;
    build_tw(tw, tid, -1.f);
    if (tid < 128) Fl[tid] = g_Fz[bi*128 + tid];
    for (int idx = tid; idx < 1024; idx += 256) Gl[idx] = g_Gz[(size_t)bi*1024 + idx];
    __syncthreads();
    #pragma unroll
    for (int k = 0; k < 8; k++){
        int idx = tid + k*256;
        int tt = idx & 15, x = idx >> 4;
        float hu = Fl[x];
        #pragma unroll
        for (int f = 0; f < 8; f++)
            hu += Gl[f*128 + x] * xi[((size_t)(b*8 + f)*128 + x)*256 + t0 + tt];
        buf[tt*128 + rev7(x)] = make_float2(hu, 0.f);
    }
    __syncthreads();
    fft_inplace(buf, 16, tw, tid, 256);
    #pragma unroll
    for (int k = 0; k < 8; k++){
        int idx = tid + k*256;
        int tt = idx & 15, xk = idx >> 4;
        int xs = (xk + 64) & 127;
        g_Hf[(size_t)xs*65536 + (size_t)bi*256 + t0 + tt] = buf[tt*128 + xk];
    }
}

// ---------------- K3: sequential CDE scan ----------------
// grid 128 (x), 1024 threads; thread = (i = warp, c = lane)
// Gauss 3-mult, b-pair f32x2 packing, double-buffered shared state, 1 sync/step
__global__ __launch_bounds__(1024, 1) void k3_scan(){
    __shared__ ulonglong2 s_zq[2][32][6];  // per j: {r01|r23, r45|r67, i.., s..}
    __shared__ float2     s_dx[2][256];    // dx[b*32+c]
    int x    = blockIdx.x;
    int tid  = threadIdx.x;
    int lane = tid & 31;   // c
    int wi   = tid >> 5;   // i (also the j-row this warp's updaters own)
    const float2* WtX = g_Wt + (size_t)x*32768 + tid;

    bool isDx  = (tid < 256);
    bool isUpd = ((lane & 1) == 0);
    int  ub    = lane >> 2;          // b owned by this updater lane
    int  ucomp = (lane >> 1) & 1;    // 0 = re, 1 = im

    float zval = 0.f;
    if (isUpd)
        zval = ((const float*)&g_Z0f[x*256 + ub*32 + wi])[ucomp];

    float2 hcur = make_float2(0.f,0.f);
    if (isDx){
        hcur = g_Hf[(size_t)x*65536 + (size_t)tid*256 + 0];
        float2 h1 = g_Hf[(size_t)x*65536 + (size_t)tid*256 + 1];
        s_dx[0][tid] = make_float2(h1.x - hcur.x, h1.y - hcur.y);
        hcur = h1;
    }
    // init zq[0]
    if (tid < 192){
        int j = tid / 6, q = tid % 6;
        int cls = q >> 1;
        int bh  = (q & 1) * 4;
        float f[4];
        #pragma unroll
        for (int w = 0; w < 4; w++){
            float2 z = g_Z0f[x*256 + (bh + w)*32 + j];
            f[w] = (cls == 0) ? z.x : (cls == 1) ? z.y : (z.x + z.y);
        }
        ulonglong2 v; v.x = pk2(f[0], f[1]); v.y = pk2(f[2], f[3]);
        s_zq[0][j][q] = v;
    }
    __syncthreads();

    bool t4 = (lane & 16) != 0, t3 = (lane & 8) != 0;
    bool t2 = (lane & 4)  != 0, t1 = (lane & 2) != 0;
    int cur = 0;

    for (int t = 0; t < 255; t++){
        // store z_t (pre-update state) and prefetch dx for t+1 into shadow buffer
        if (isUpd){
            float im = __shfl_xor_sync(0x55555555u, zval, 2);
            if (ucomp == 0)
                g_Zs[(size_t)(ub*32 + wi)*32768 + (size_t)t*128 + x] = make_float2(zval, im);
        }
        if (isDx){
            int tn = (t + 2 < 256) ? t + 2 : 255;
            float2 h2 = g_Hf[(size_t)x*65536 + (size_t)tid*256 + tn];
            s_dx[cur ^ 1][tid] = make_float2(h2.x - hcur.x, h2.y - hcur.y);
            hcur = h2;
        }

        // P = sum wr*zr ; Q = sum wi*zi ; S = sum (wr+wi)*(zr+zi)
        U64 P[4] = {0,0,0,0}, Q[4] = {0,0,0,0}, S[4] = {0,0,0,0};
        const ulonglong2 (*zq)[6] = s_zq[cur];
        #pragma unroll 4
        for (int j = 0; j < 32; j++){
            float2 w = WtX[(size_t)j*1024];
            U64 wrr = pk2(w.x, w.x);
            U64 wii = pk2(w.y, w.y);
            float ws = w.x + w.y;
            U64 wss = pk2(ws, ws);
            ulonglong2 zr2a = zq[j][0], zr2b = zq[j][1];
            ulonglong2 zi2a = zq[j][2], zi2b = zq[j][3];
            ulonglong2 zs2a = zq[j][4], zs2b = zq[j][5];
            FMA2(P[0], wrr, zr2a.x); FMA2(P[1], wrr, zr2a.y);
            FMA2(P[2], wrr, zr2b.x); FMA2(P[3], wrr, zr2b.y);
            FMA2(Q[0], wii, zi2a.x); FMA2(Q[1], wii, zi2a.y);
            FMA2(Q[2], wii, zi2b.x); FMA2(Q[3], wii, zi2b.y);
            FMA2(S[0], wss, zs2a.x); FMA2(S[1], wss, zs2a.y);
            FMA2(S[2], wss, zs2b.x); FMA2(S[3], wss, zs2b.y);
        }

        // epilogue: fz = (P-Q) + i(S-P-Q); contrib = fz * dx[b, c]
        float v[16];
        #pragma unroll
        for (int k = 0; k < 4; k++){
            float2 p = upk2(P[k]), q = upk2(Q[k]), s = upk2(S[k]);
            int b0 = 2*k, b1 = 2*k + 1;
            float fr0 = p.x - q.x, fi0 = s.x - p.x - q.x;
            float fr1 = p.y - q.y, fi1 = s.y - p.y - q.y;
            float2 d0 = s_dx[cur][b0*32 + lane];
            float2 d1 = s_dx[cur][b1*32 + lane];
            v[b0*2]     = fr0*d0.x - fi0*d0.y;
            v[b0*2 + 1] = fr0*d0.y + fi0*d0.x;
            v[b1*2]     = fr1*d1.x - fi1*d1.y;
            v[b1*2 + 1] = fr1*d1.y + fi1*d1.x;
        }

        // value-halving butterfly: 16 sums over 32 lanes (31 shfl)
        #pragma unroll
        for (int m = 0; m < 8; m++){
            float a0 = v[m]     + __shfl_xor_sync(0xffffffffu, v[m],     16);
            float a1 = v[m + 8] + __shfl_xor_sync(0xffffffffu, v[m + 8], 16);
            v[m] = t4 ? a1 : a0;
        }
        #pragma unroll
        for (int m = 0; m < 4; m++){
            float a0 = v[m]     + __shfl_xor_sync(0xffffffffu, v[m],     8);
            float a1 = v[m + 4] + __shfl_xor_sync(0xffffffffu, v[m + 4], 8);
            v[m] = t3 ? a1 : a0;
        }
        #pragma unroll
        for (int m = 0; m < 2; m++){
            float a0 = v[m]     + __shfl_xor_sync(0xffffffffu, v[m],     4);
            float a1 = v[m + 2] + __shfl_xor_sync(0xffffffffu, v[m + 2], 4);
            v[m] = t2 ? a1 : a0;
        }
        {
            float a0 = v[0] + __shfl_xor_sync(0xffffffffu, v[0], 2);
            float a1 = v[1] + __shfl_xor_sync(0xffffffffu, v[1], 2);
            v[0] = t1 ? a1 : a0;
        }
        v[0] += __shfl_xor_sync(0xffffffffu, v[0], 1);
        // even lane l holds total for b = l>>2, comp = (l>>1)&1

        // update state into shadow buffer (readers are on s_zq[cur])
        if (isUpd){
            zval += v[0];
            float* zqf = (float*)&s_zq[cur ^ 1][wi][0];
            zqf[ucomp*8 + ub] = zval;
            float other = __shfl_xor_sync(0x55555555u, zval, 2);
            if (ucomp == 0) zqf[16 + ub] = zval + other;
        }
        __syncthreads();
        cur ^= 1;
    }
    // final state t = 255
    if (isUpd){
        float im = __shfl_xor_sync(0x55555555u, zval, 2);
        if (ucomp == 0)
            g_Zs[(size_t)(ub*32 + wi)*32768 + (size_t)255*128 + x] = make_float2(zval, im);
    }
}

// ---------------- K4 ----------------
__global__ void k4_ifft(float* __restrict__ out){
    __shared__ float2 buf[16*128];
    __shared__ float2 tw[64];
    int bi = blockIdx.x;
    int t0 = blockIdx.y * 16;
    int tid = threadIdx.x;
    build_tw(tw, tid, +1.f);
    #pragma unroll
    for (int k = 0; k < 8; k++){
        int idx = tid + k*256;
        int m = idx & 127, tt = idx >> 7;
        float2 v = g_Zs[(size_t)bi*32768 + (size_t)(t0 + tt)*128 + ((m + 64) & 127)];
        buf[tt*128 + rev7(m)] = v;
    }
    __syncthreads();
    fft_inplace(buf, 16, tw, tid, 256);
    #pragma unroll
    for (int k = 0; k < 8; k++){
        int idx = tid + k*256;
        int tt = idx & 15, n = idx >> 4;
        out[((size_t)bi*128 + n)*256 + t0 + tt] = buf[tt*128 + n].x * (1.0f/128.0f);
    }
}

// ---------------- launch ----------------
extern "C" void kernel_launch(void* const* d_in, const int* in_sizes, int n_in,
                              void* d_out, int out_size){
    const float* z0 = (const float*)d_in[0];
    const float* xi = (const float*)d_in[1];
    const float* A  = (const float*)d_in[2];
    const float* Gw = (const float*)d_in[3];
    const float* Wr = (const float*)d_in[4];
    const float* Wi = (const float*)d_in[5];
    float* out = (float*)d_out;

    k0_wt<<<dim3(128, 32), 1024>>>(Wr, Wi);
    k1_proj<<<256, 128>>>(z0, A, Gw);
    k2b_z0fft<<<256, 128>>>(z0);
    k2_hufft<<<dim3(256, 16), 256>>>(xi);
    k3_scan<<<128, 1024>>>();
    k4_ifft<<<dim3(256, 16), 256>>>(out);
    (void)in_sizes; (void)n_in; (void)out_size;
}